// round 3
// baseline (speedup 1.0000x reference)
#include <cuda_runtime.h>
#include <math.h>

#define DT_F 0.1f
#define MAX_BLOCKS 8192

__device__ double g_partials[MAX_BLOCKS];
__device__ unsigned int g_ticket = 0;   // self-resetting; 0 at every replay start

__global__ void __launch_bounds__(256) fused_kernel(
    const float* __restrict__ para,
    const float* __restrict__ omega,
    const float* __restrict__ infd,
    float* __restrict__ out,
    int npairs, int ndata)
{
    // ---- per-block constant computation (replaces prep kernel) ----
    float x00 = __ldg(para + 0), x01 = __ldg(para + 1);
    float x10 = __ldg(para + 2), x11 = __ldg(para + 3);
    float a    = 0.5f * (x00 - x11);
    float rez  = 0.5f + 0.5f * (x01 + x10);   // includes model H coupling 0.5
    float imz  = 0.5f * (x01 - x10);
    float rsq  = a * a + rez * rez + imz * imz;
    float r    = sqrtf(fmaxf(rsq, 1e-30f));
    float c    = rez * rez;

    // ---- main pass: grid-stride over row pairs ----
    double local = 0.0;
    const int stride = gridDim.x * blockDim.x;
    for (int t = blockIdx.x * blockDim.x + threadIdx.x; t < npairs; t += stride) {
        const float4* om4 = reinterpret_cast<const float4*>(omega) + (size_t)t * 5;
        float4 v0 = om4[0];
        float4 v1 = om4[1];
        float4 v2 = om4[2];
        float4 v3 = om4[3];
        float4 v4 = om4[4];
        float2 f  = reinterpret_cast<const float2*>(infd)[t];

        float s0 = ((v0.x + v0.y) + (v0.z + v0.w))
                 + ((v1.x + v1.y) + (v1.z + v1.w))
                 + (v2.x + v2.y);
        float s1 = (v2.z + v2.w)
                 + ((v3.x + v3.y) + (v3.z + v3.w))
                 + ((v4.x + v4.y) + (v4.z + v4.w));

        {
            float phi   = DT_F * s0;
            float theta = phi * r;
            float sinc  = (rsq > 1e-24f) ? (sinf(theta) / r) : phi;
            float infid = 1.0f - sinc * sinc * c;
            float d     = f.x - infid;
            local += (double)(d * d);
        }
        {
            float phi   = DT_F * s1;
            float theta = phi * r;
            float sinc  = (rsq > 1e-24f) ? (sinf(theta) / r) : phi;
            float infid = 1.0f - sinc * sinc * c;
            float d     = f.y - infid;
            local += (double)(d * d);
        }
    }

    // ---- block reduction ----
    #pragma unroll
    for (int off = 16; off > 0; off >>= 1)
        local += __shfl_down_sync(0xFFFFFFFFu, local, off);

    __shared__ double warp_sums[8];
    int lane = threadIdx.x & 31;
    int wid  = threadIdx.x >> 5;
    if (lane == 0) warp_sums[wid] = local;
    __syncthreads();

    __shared__ bool s_is_last;
    if (wid == 0) {
        double v = (lane < (blockDim.x >> 5)) ? warp_sums[lane] : 0.0;
        #pragma unroll
        for (int off = 4; off > 0; off >>= 1)
            v += __shfl_down_sync(0xFFFFFFFFu, v, off);
        if (lane == 0) {
            g_partials[blockIdx.x] = v;
            __threadfence();
            unsigned int tk = atomicAdd(&g_ticket, 1u);
            s_is_last = (tk == gridDim.x - 1);
        }
    }
    __syncthreads();

    // ---- last block finalizes ----
    if (s_is_last) {
        double v = 0.0;
        for (int i = threadIdx.x; i < gridDim.x; i += blockDim.x)
            v += g_partials[i];
        #pragma unroll
        for (int off = 16; off > 0; off >>= 1)
            v += __shfl_down_sync(0xFFFFFFFFu, v, off);
        if (lane == 0) warp_sums[wid] = v;
        __syncthreads();
        if (wid == 0) {
            double w = (lane < (blockDim.x >> 5)) ? warp_sums[lane] : 0.0;
            #pragma unroll
            for (int off = 4; off > 0; off >>= 1)
                w += __shfl_down_sync(0xFFFFFFFFu, w, off);
            if (lane == 0) {
                out[0] = (float)(w / (double)ndata);
                g_ticket = 0;   // reset for next graph replay
            }
        }
    }
}

extern "C" void kernel_launch(void* const* d_in, const int* in_sizes, int n_in,
                              void* d_out, int out_size) {
    const float* para  = (const float*)d_in[0];
    const float* omega = (const float*)d_in[1];
    const float* infd  = (const float*)d_in[2];
    float* out = (float*)d_out;

    int ndata  = in_sizes[2];
    int npairs = ndata / 2;

    int threads = 256;
    int blocks  = (npairs + threads - 1) / threads;
    if (blocks > MAX_BLOCKS) blocks = MAX_BLOCKS;

    fused_kernel<<<blocks, threads>>>(para, omega, infd, out, npairs, ndata);
}